// round 3
// baseline (speedup 1.0000x reference)
#include <cuda_runtime.h>
#include <stdint.h>

// Problem constants (fixed shapes per reference)
#define VOCAB   20000
#define TOPK    8
#define GLOVE   300
#define ROW_F   (TOPK * 2 * GLOVE)   // 4800 floats per vocab row
#define OUTC    100
#define B       32
#define L       128
#define NLAB    8
#define NPOS    (B * L)              // 4096
#define NLABTOT (NPOS * NLAB)        // 32768

// Device scratch (no allocations allowed)
__device__ unsigned int g_flags[VOCAB];
__device__ float g_lsum[VOCAB * GLOVE];   // 24 MB: per-vocab summed+prescaled 300-vec
__device__ float g_A[NPOS * GLOVE];       // 4.9 MB: per-position averaged 300-vec

// ---------------------------------------------------------------------------
// Kernel 1: clear usage flags
// ---------------------------------------------------------------------------
__global__ void k_clear_flags() {
    int i = blockIdx.x * blockDim.x + threadIdx.x;
    if (i < VOCAB) g_flags[i] = 0u;
}

// ---------------------------------------------------------------------------
// Kernel 2: mark used vocab entries
// ---------------------------------------------------------------------------
__global__ void k_mark_flags(const int* __restrict__ labels) {
    int i = blockIdx.x * blockDim.x + threadIdx.x;
    if (i < NLABTOT) g_flags[labels[i]] = 1u;
}

// ---------------------------------------------------------------------------
// Kernel 3: per-vocab row reduction (DRAM-streaming bound, ~310 MB total).
// __ldcs: evict-first streaming so the table stream does NOT evict g_lsum
// from L2 (g_lsum must stay resident for k_gather).
// ---------------------------------------------------------------------------
__global__ __launch_bounds__(256) void k_rowsum(const float* __restrict__ table) {
    const int v = blockIdx.x;
    if (!g_flags[v]) return;
    const float* __restrict__ row = table + (size_t)v * ROW_F;
    const int t = threadIdx.x;
    const float scale = 1.0f / 128.0f;

    {
        float s = 0.0f;
        #pragma unroll
        for (int r = 0; r < 16; ++r) s += __ldcs(&row[r * GLOVE + t]);
        g_lsum[v * GLOVE + t] = s * scale;
    }
    if (t < GLOVE - 256) {
        const int d = t + 256;
        float s = 0.0f;
        #pragma unroll
        for (int r = 0; r < 16; ++r) s += __ldcs(&row[r * GLOVE + d]);
        g_lsum[v * GLOVE + d] = s * scale;
    }
}

// ---------------------------------------------------------------------------
// Kernel 4: averaging gather. One float4 per thread: 4096*75 = 307200 threads.
// g_lsum is L2-resident (thanks to __ldcs in rowsum) -> pure L2 gather.
// ---------------------------------------------------------------------------
#define GATHER_THREADS 256
#define GATHER_TOTAL   (NPOS * (GLOVE / 4))   // 307200

__global__ __launch_bounds__(GATHER_THREADS) void k_gather(const int* __restrict__ labels) {
    const int i = blockIdx.x * GATHER_THREADS + threadIdx.x;
    if (i >= GATHER_TOTAL) return;
    const int p  = i / (GLOVE / 4);
    const int k  = (i % (GLOVE / 4)) * 4;

    const int* __restrict__ lab = labels + p * NLAB;
    int l[NLAB];
    #pragma unroll
    for (int j = 0; j < NLAB; ++j) l[j] = lab[j];

    float4 s = make_float4(0.f, 0.f, 0.f, 0.f);
    #pragma unroll
    for (int j = 0; j < NLAB; ++j) {
        const float4 v = *reinterpret_cast<const float4*>(&g_lsum[l[j] * GLOVE + k]);
        s.x += v.x; s.y += v.y; s.z += v.z; s.w += v.w;
    }
    *reinterpret_cast<float4*>(&g_A[p * GLOVE + k]) = s;
}

// ---------------------------------------------------------------------------
// Kernel 5 (v3): GEMM  out[4096,100] = A[4096,300] * W^T + bias.
// Block: 32 pos x 100 outs, 200 threads = (8 pos-groups x 4 pos) x (25 out-
// groups x 4 outs). Whole W (transposed, pitch 102) + whole A tile staged in
// 161KB dynamic smem once; single __syncthreads.
// Inner loop: packed f32x2 FMA over the out dimension -> 8 FFMA2 per k per
// thread instead of 16 FFMA. W pairs load directly as 64-bit LDS; A values
// broadcast-loaded and duplicated via mov.b64.
// ---------------------------------------------------------------------------
#define GP3      32
#define GT3      200
#define WPITCH3  102                         // even -> 8B-aligned 64-bit LDS
#define SMEM_W   (GLOVE * WPITCH3)           // 30600 floats
#define SMEM_A   (GP3 * GLOVE)               // 9600 floats
#define SMEM_BYTES ((SMEM_W + SMEM_A) * 4)   // 160800 B

#define FMA2(acc, a, w) \
    asm("fma.rn.f32x2 %0, %1, %2, %0;" : "+l"(acc) : "l"(a), "l"(w))
#define DUP2(d, s) \
    asm("mov.b64 %0, {%1, %1};" : "=l"(d) : "f"(s))
#define UNPK2(lo, hi, v) \
    asm("mov.b64 {%0, %1}, %2;" : "=f"(lo), "=f"(hi) : "l"(v))

__global__ __launch_bounds__(GT3) void k_gemm3(
    const float* __restrict__ w,      // [100, 300]
    const float* __restrict__ bias,   // [100]
    float* __restrict__ out)          // [4096, 100]
{
    extern __shared__ float sh[];
    float* W_sh = sh;                 // [300][102] transposed: [k][o]
    float* A_sh = sh + SMEM_W;        // [32][300] row-major

    const int tid   = threadIdx.x;
    const int pbase = blockIdx.x * GP3;
    const int pgrp  = tid / 25;       // 0..7 -> pos = pgrp*4 + p
    const int ogrp  = tid % 25;       // 0..24 -> outs = ogrp*4 + {0..3}

    // Stage W transposed (coalesced global reads, 2-way-max STS conflicts)
    #pragma unroll 4
    for (int o = 0; o < OUTC; ++o)
        for (int kk = tid; kk < GLOVE; kk += GT3)
            W_sh[kk * WPITCH3 + o] = w[o * GLOVE + kk];

    // Stage A tile (coalesced, conflict-free)
    #pragma unroll 4
    for (int pp = 0; pp < GP3; ++pp)
        for (int kk = tid; kk < GLOVE; kk += GT3)
            A_sh[pp * GLOVE + kk] = g_A[(pbase + pp) * GLOVE + kk];

    __syncthreads();

    unsigned long long acc[4][2];
    #pragma unroll
    for (int p = 0; p < 4; ++p) { acc[p][0] = 0ull; acc[p][1] = 0ull; }

    const float* a0p = A_sh + (pgrp * 4 + 0) * GLOVE;
    const float* a1p = A_sh + (pgrp * 4 + 1) * GLOVE;
    const float* a2p = A_sh + (pgrp * 4 + 2) * GLOVE;
    const float* a3p = A_sh + (pgrp * 4 + 3) * GLOVE;
    const float* wp  = W_sh + ogrp * 4;

    #pragma unroll 4
    for (int kk = 0; kk < GLOVE; ++kk) {
        const unsigned long long w01 =
            *reinterpret_cast<const unsigned long long*>(wp + kk * WPITCH3);
        const unsigned long long w23 =
            *reinterpret_cast<const unsigned long long*>(wp + kk * WPITCH3 + 2);
        float a0 = a0p[kk], a1 = a1p[kk], a2 = a2p[kk], a3 = a3p[kk];
        unsigned long long d0, d1, d2, d3;
        DUP2(d0, a0); DUP2(d1, a1); DUP2(d2, a2); DUP2(d3, a3);
        FMA2(acc[0][0], d0, w01); FMA2(acc[0][1], d0, w23);
        FMA2(acc[1][0], d1, w01); FMA2(acc[1][1], d1, w23);
        FMA2(acc[2][0], d2, w01); FMA2(acc[2][1], d2, w23);
        FMA2(acc[3][0], d3, w01); FMA2(acc[3][1], d3, w23);
    }

    // Epilogue: unpack, add bias, vectorized store
    const float4 bv = *reinterpret_cast<const float4*>(&bias[ogrp * 4]);
    #pragma unroll
    for (int p = 0; p < 4; ++p) {
        float r0, r1, r2, r3;
        UNPK2(r0, r1, acc[p][0]);
        UNPK2(r2, r3, acc[p][1]);
        float4 res = make_float4(r0 + bv.x, r1 + bv.y, r2 + bv.z, r3 + bv.w);
        const int pos = pbase + pgrp * 4 + p;
        *reinterpret_cast<float4*>(&out[pos * OUTC + ogrp * 4]) = res;
    }
}

// ---------------------------------------------------------------------------
extern "C" void kernel_launch(void* const* d_in, const int* in_sizes, int n_in,
                              void* d_out, int out_size) {
    const int*   labels = (const int*)  d_in[0];   // [32, 128, 8] int32
    const float* table  = (const float*)d_in[1];   // [20000, 8, 600] f32
    const float* conv_w = (const float*)d_in[2];   // [100, 300]
    const float* conv_b = (const float*)d_in[3];   // [100]
    float*       out    = (float*)d_out;           // [32, 128, 100]

    (void)in_sizes; (void)n_in; (void)out_size;

    cudaFuncSetAttribute(k_gemm3, cudaFuncAttributeMaxDynamicSharedMemorySize,
                         SMEM_BYTES);

    k_clear_flags<<<(VOCAB + 255) / 256, 256>>>();
    k_mark_flags<<<(NLABTOT + 255) / 256, 256>>>(labels);
    k_rowsum<<<VOCAB, 256>>>(table);
    k_gather<<<(GATHER_TOTAL + GATHER_THREADS - 1) / GATHER_THREADS, GATHER_THREADS>>>(labels);
    k_gemm3<<<NPOS / GP3, GT3, SMEM_BYTES>>>(conv_w, conv_b, out);
}